// round 3
// baseline (speedup 1.0000x reference)
#include <cuda_runtime.h>
#include <math.h>
#include <float.h>

#define NB 32
#define NS 32768
#define NF 128
#define DM 128

// ------------------------- scratch (device globals) -------------------------
__device__ float2 g_x2[NB * NS];          // (hi, lo) tf32 split of x
__device__ float2 g_w2[128 * 512];        // (hi, lo) tf32 split of fb
__device__ float g_chunk[NB * NF * DM];   // pooled half-window sums (already /512)
__device__ float g_h[NB * NF * DM];
__device__ float g_qkv[NB * NF * 384];
__device__ float g_attno[NB * NF * DM];
__device__ float g_tmp[NB * NF * DM];
__device__ float g_ff[NB * NF * DM];
__device__ int   g_topidx[NB * 16];
__device__ float g_topval[NB * 16];

// ------------------------- helpers ------------------------------------------
__device__ __forceinline__ unsigned to_tf32(float x) {
    unsigned r; asm("cvt.rna.tf32.f32 %0, %1;" : "=r"(r) : "f"(x)); return r;
}

__device__ __forceinline__ void mma_tf32(float& d0, float& d1, float& d2, float& d3,
                                         unsigned a0, unsigned a1, unsigned a2, unsigned a3,
                                         unsigned b0, unsigned b1)
{
    asm volatile("mma.sync.aligned.m16n8k8.row.col.f32.tf32.tf32.f32 "
                 "{%0,%1,%2,%3}, {%4,%5,%6,%7}, {%8,%9}, {%0,%1,%2,%3};"
                 : "+f"(d0), "+f"(d1), "+f"(d2), "+f"(d3)
                 : "r"(a0), "r"(a1), "r"(a2), "r"(a3), "r"(b0), "r"(b1));
}

#define CP_ASYNC16(dst_smem, src) \
    asm volatile("cp.async.ca.shared.global [%0], [%1], 16;" :: "r"(dst_smem), "l"(src))
#define CP_COMMIT() asm volatile("cp.async.commit_group;")
#define CP_WAIT(n)  asm volatile("cp.async.wait_group %0;" :: "n"(n))

// ------------------------- tf32 split precompute -----------------------------
__global__ void split_x_kernel(const float* __restrict__ x) {
    int i = blockIdx.x * 256 + threadIdx.x;
    if (i < NB * NS) {
        float v = x[i];
        unsigned hb = to_tf32(v);
        float hi = __uint_as_float(hb);
        unsigned lb = to_tf32(v - hi);
        g_x2[i] = make_float2(hi, __uint_as_float(lb));
    }
}
__global__ void split_w_kernel(const float* __restrict__ fb) {
    int i = blockIdx.x * 256 + threadIdx.x;
    if (i < 128 * 512) {
        float v = fb[i];
        unsigned hb = to_tf32(v);
        float hi = __uint_as_float(hb);
        unsigned lb = to_tf32(v - hi);
        g_w2[i] = make_float2(hi, __uint_as_float(lb));
    }
}

// ------------------------- conv (3xTF32 mma) + |.| + pool --------------------
// Per block (h, b): y[t, c] = sum_k xwin[t+k] * w[c,k], t in [0,256), c in [0,128),
// then g_chunk[b,h,c] = sum_t |y| / 512.
#define WPAD 68                          // float2 per padded weight row
#define SLAB_F2 (128 * WPAD)             // one K=64 weight slab (padded)
#define CONV_SMEM ((2 * SLAB_F2 + 768) * 8 + 128 * 4)

__global__ __launch_bounds__(512, 1) void conv_mma_kernel(const float* __restrict__ dummy)
{
    extern __shared__ __align__(16) float2 smem2[];
    float2* ws[2] = { smem2, smem2 + SLAB_F2 };
    float2* xs2 = smem2 + 2 * SLAB_F2;               // 768 float2
    float* csum = (float*)(smem2 + 2 * SLAB_F2 + 768);

    const int h = blockIdx.x, b = blockIdx.y;
    const int tid = threadIdx.x;
    const int w = tid >> 5, lane = tid & 31;
    const int gid = lane >> 2, tig = lane & 3;
    const int tbase = (w >> 2) * 64;                 // warp t-tile
    const int cbase = (w & 3) * 32;                  // warp c-tile
    const int t0 = h << 8;

    // x window (hi,lo): global indices t0-256 .. t0+511
    const float2* xb = g_x2 + (size_t)b * NS;
    for (int i = tid; i < 768; i += 512) {
        int g = t0 - 256 + i;
        xs2[i] = (g >= 0 && g < NS) ? xb[g] : make_float2(0.f, 0.f);
    }
    if (tid < 128) csum[tid] = 0.f;

    // slab loader: K-slab s covers k in [64s, 64s+64)
    unsigned ws_base[2];
    ws_base[0] = (unsigned)__cvta_generic_to_shared(ws[0]);
    ws_base[1] = (unsigned)__cvta_generic_to_shared(ws[1]);
    auto load_slab = [&](int buf, int k0) {
        for (int q = tid; q < 4096; q += 512) {
            int c = q >> 5, j = q & 31;                       // j: pair of float2
            unsigned dst = ws_base[buf] + (unsigned)(c * WPAD + 2 * j) * 8;
            const float2* src = g_w2 + (size_t)c * 512 + k0 + 2 * j;
            CP_ASYNC16(dst, src);
        }
    };

    float d[4][4][4];
#pragma unroll
    for (int m = 0; m < 4; m++)
#pragma unroll
        for (int n = 0; n < 4; n++)
#pragma unroll
            for (int r = 0; r < 4; r++) d[m][n][r] = 0.f;

    load_slab(0, 0);
    CP_COMMIT();

    for (int s = 0; s < 8; s++) {
        if (s < 7) { load_slab((s + 1) & 1, (s + 1) * 64); CP_COMMIT(); CP_WAIT(1); }
        else       { CP_WAIT(0); }
        __syncthreads();
        const float2* wsb = ws[s & 1];
#pragma unroll
        for (int k8 = 0; k8 < 8; k8++) {
            const int kb = k8 * 8;
            unsigned bh0[4], bl0[4], bh1[4], bl1[4];
#pragma unroll
            for (int n = 0; n < 4; n++) {
                const float2* wr = wsb + (size_t)(cbase + 8 * n + gid) * WPAD + kb + tig;
                float2 v0 = wr[0];
                float2 v1 = wr[4];
                bh0[n] = __float_as_uint(v0.x); bl0[n] = __float_as_uint(v0.y);
                bh1[n] = __float_as_uint(v1.x); bl1[n] = __float_as_uint(v1.y);
            }
            const int ib = tbase + gid + 64 * s + kb + tig;
#pragma unroll
            for (int m = 0; m < 4; m++) {
                float2 va0 = xs2[ib + 16 * m];
                float2 va1 = xs2[ib + 16 * m + 8];
                float2 va2 = xs2[ib + 16 * m + 4];
                float2 va3 = xs2[ib + 16 * m + 12];
                unsigned ah0 = __float_as_uint(va0.x), al0 = __float_as_uint(va0.y);
                unsigned ah1 = __float_as_uint(va1.x), al1 = __float_as_uint(va1.y);
                unsigned ah2 = __float_as_uint(va2.x), al2 = __float_as_uint(va2.y);
                unsigned ah3 = __float_as_uint(va3.x), al3 = __float_as_uint(va3.y);
#pragma unroll
                for (int n = 0; n < 4; n++) {
                    mma_tf32(d[m][n][0], d[m][n][1], d[m][n][2], d[m][n][3],
                             ah0, ah1, ah2, ah3, bh0[n], bh1[n]);
                    mma_tf32(d[m][n][0], d[m][n][1], d[m][n][2], d[m][n][3],
                             ah0, ah1, ah2, ah3, bl0[n], bl1[n]);
                    mma_tf32(d[m][n][0], d[m][n][1], d[m][n][2], d[m][n][3],
                             al0, al1, al2, al3, bh0[n], bh1[n]);
                }
            }
        }
        __syncthreads();
    }

    // epilogue: abs + sum over t, pooled per channel
    float sacc[4][2];
#pragma unroll
    for (int n = 0; n < 4; n++) {
        sacc[n][0] = 0.f; sacc[n][1] = 0.f;
#pragma unroll
        for (int m = 0; m < 4; m++) {
            sacc[n][0] += fabsf(d[m][n][0]) + fabsf(d[m][n][2]);
            sacc[n][1] += fabsf(d[m][n][1]) + fabsf(d[m][n][3]);
        }
    }
    // reduce over gid (lane bits 2..4)
#pragma unroll
    for (int off = 4; off <= 16; off <<= 1)
#pragma unroll
        for (int n = 0; n < 4; n++) {
            sacc[n][0] += __shfl_xor_sync(0xffffffffu, sacc[n][0], off);
            sacc[n][1] += __shfl_xor_sync(0xffffffffu, sacc[n][1], off);
        }
    if (lane < 4) {
#pragma unroll
        for (int n = 0; n < 4; n++) {
            atomicAdd(&csum[cbase + 8 * n + 2 * tig + 0], sacc[n][0]);
            atomicAdd(&csum[cbase + 8 * n + 2 * tig + 1], sacc[n][1]);
        }
    }
    __syncthreads();
    if (tid < 128)
        g_chunk[((size_t)b * NF + h) * DM + tid] = csum[tid] * (1.f / 512.f);
}

// ---------------- frames + pos-encoding + embed -----------------------------
__global__ __launch_bounds__(128) void embed_kernel(const float* __restrict__ ew,
                                                    const float* __restrict__ eb)
{
    const int row = blockIdx.x;         // b*128 + t
    const int t = row & 127;
    const int tid = threadIdx.x;
    __shared__ float vec[161];
    {
        float f = g_chunk[(size_t)row * DM + tid];
        if (t > 0) f += g_chunk[(size_t)(row - 1) * DM + tid];
        vec[tid] = f;
    }
    if (tid < 33) {
        float pos = (t == 127) ? 1.0f
                               : __fadd_rn(-1.0f, __fmul_rn((float)t, __fdiv_rn(2.0f, 127.0f)));
        float v;
        if (tid == 0) v = pos;
        else {
            int k = (tid <= 16) ? (tid - 1) : (tid - 17);
            float fr = __fmul_rn(exp2f((float)k), 3.14159274101257324f);
            float prod = __fmul_rn(pos, fr);
            v = (tid <= 16) ? (float)sin((double)prod) : (float)cos((double)prod);
        }
        vec[128 + tid] = v;
    }
    __syncthreads();
    float a = eb[tid];
    const float* w = ew + (size_t)tid * 161;
    for (int j = 0; j < 161; j++) a = fmaf(vec[j], w[j], a);
    g_h[(size_t)row * DM + tid] = a;
}

// ---------------- generic row-blocked linear (K = 128) ----------------------
template <int NO, bool RELU>
__global__ __launch_bounds__(128) void linear_kernel(const float* __restrict__ in,
                                                     const float* __restrict__ W,
                                                     const float* __restrict__ bias,
                                                     float* __restrict__ out)
{
    const int row0 = blockIdx.x << 3;
    const int tid = threadIdx.x;
    __shared__ __align__(16) float sv[8 * DM];
#pragma unroll
    for (int r = 0; r < 8; r++) sv[r * DM + tid] = in[(size_t)(row0 + r) * DM + tid];
    __syncthreads();

    float acc[NO][8];
#pragma unroll
    for (int o = 0; o < NO; o++) {
        float bv = bias[o * DM + tid];
#pragma unroll
        for (int r = 0; r < 8; r++) acc[o][r] = bv;
    }
    const float4* sv4 = (const float4*)sv;
    const float4* W4 = (const float4*)W;
    for (int j4 = 0; j4 < 32; j4++) {
        float4 wv[NO];
#pragma unroll
        for (int o = 0; o < NO; o++) wv[o] = W4[(size_t)(o * DM + tid) * 32 + j4];
#pragma unroll
        for (int r = 0; r < 8; r++) {
            float4 xv = sv4[r * 32 + j4];
#pragma unroll
            for (int o = 0; o < NO; o++) {
                acc[o][r] = fmaf(wv[o].x, xv.x, acc[o][r]);
                acc[o][r] = fmaf(wv[o].y, xv.y, acc[o][r]);
                acc[o][r] = fmaf(wv[o].z, xv.z, acc[o][r]);
                acc[o][r] = fmaf(wv[o].w, xv.w, acc[o][r]);
            }
        }
    }
#pragma unroll
    for (int r = 0; r < 8; r++)
#pragma unroll
        for (int o = 0; o < NO; o++) {
            float v = acc[o][r];
            if (RELU) v = fmaxf(v, 0.f);
            out[(size_t)(row0 + r) * (NO * DM) + o * DM + tid] = v;
        }
}

// ---------------- attention (one block per (head, batch)) -------------------
__global__ __launch_bounds__(128) void attn_kernel()
{
    const int hd = blockIdx.x, b = blockIdx.y;
    const int tid = threadIdx.x;
    __shared__ __align__(16) float ks[NF * 32];
    __shared__ __align__(16) float vs[NF * 32];
    const float* base = g_qkv + (size_t)b * NF * 384;

    for (int idx = tid; idx < NF * 32; idx += 128) {
        int j = idx >> 5, i = idx & 31;
        ks[idx] = base[j * 384 + 128 + hd * 32 + i];
        vs[idx] = base[j * 384 + 256 + hd * 32 + i];
    }
    float q[32];
    {
        const float4* qp = (const float4*)(base + (size_t)tid * 384 + hd * 32);
#pragma unroll
        for (int i = 0; i < 8; i++) {
            float4 v = qp[i];
            q[4 * i] = v.x; q[4 * i + 1] = v.y; q[4 * i + 2] = v.z; q[4 * i + 3] = v.w;
        }
    }
    __syncthreads();

    float o[32];
#pragma unroll
    for (int i = 0; i < 32; i++) o[i] = 0.f;
    float m = -FLT_MAX, l = 0.f;
    const float scale = 0.17677669529663689f;

    for (int j = 0; j < NF; j++) {
        const float4* kp = (const float4*)(ks + j * 32);
        float s = 0.f;
#pragma unroll
        for (int i = 0; i < 8; i++) {
            float4 kv = kp[i];
            s = fmaf(q[4 * i], kv.x, s); s = fmaf(q[4 * i + 1], kv.y, s);
            s = fmaf(q[4 * i + 2], kv.z, s); s = fmaf(q[4 * i + 3], kv.w, s);
        }
        s *= scale;
        float mn = fmaxf(m, s);
        float c = expf(m - mn);
        float p = expf(s - mn);
        l = l * c + p;
        const float4* vp = (const float4*)(vs + j * 32);
#pragma unroll
        for (int i = 0; i < 8; i++) {
            float4 vv = vp[i];
            o[4 * i]     = o[4 * i] * c + p * vv.x;
            o[4 * i + 1] = o[4 * i + 1] * c + p * vv.y;
            o[4 * i + 2] = o[4 * i + 2] * c + p * vv.z;
            o[4 * i + 3] = o[4 * i + 3] * c + p * vv.w;
        }
        m = mn;
    }
    float inv = 1.f / l;
    float* dst = g_attno + (size_t)(b * NF + tid) * DM + hd * 32;
#pragma unroll
    for (int i = 0; i < 32; i++) dst[i] = o[i] * inv;
}

// ---------------- residual add + layernorm ----------------------------------
__global__ __launch_bounds__(128) void addln_kernel(float* __restrict__ hbuf,
                                                    const float* __restrict__ tbuf,
                                                    const float* __restrict__ w,
                                                    const float* __restrict__ bias)
{
    const int row = blockIdx.x, tid = threadIdx.x;
    __shared__ float sb[4];
    float v = hbuf[(size_t)row * DM + tid] + tbuf[(size_t)row * DM + tid];
    float s = v;
#pragma unroll
    for (int o = 16; o; o >>= 1) s += __shfl_xor_sync(0xffffffffu, s, o);
    if ((tid & 31) == 0) sb[tid >> 5] = s;
    __syncthreads();
    float mean = (sb[0] + sb[1] + sb[2] + sb[3]) * 0.0078125f;
    float dv = v - mean;
    float s2 = dv * dv;
#pragma unroll
    for (int o = 16; o; o >>= 1) s2 += __shfl_xor_sync(0xffffffffu, s2, o);
    __syncthreads();
    if ((tid & 31) == 0) sb[tid >> 5] = s2;
    __syncthreads();
    float var = (sb[0] + sb[1] + sb[2] + sb[3]) * 0.0078125f;
    float r = 1.f / sqrtf(var + 1e-5f);
    hbuf[(size_t)row * DM + tid] = dv * r * w[tid] + bias[tid];
}

// ---------------- attention scores + top-16 ---------------------------------
__global__ __launch_bounds__(128) void topk_kernel(const float* __restrict__ attn_w,
                                                   const float* __restrict__ attn_b)
{
    const int b = blockIdx.x, tid = threadIdx.x;
    __shared__ float sv[128];
    __shared__ float rv[128];
    __shared__ int ri[128];
    const float4* hp = (const float4*)(g_h + (size_t)(b * NF + tid) * DM);
    const float4* wp = (const float4*)attn_w;
    float s = attn_b[0];
#pragma unroll
    for (int i = 0; i < 32; i++) {
        float4 h4 = hp[i], w4 = wp[i];
        s = fmaf(h4.x, w4.x, s); s = fmaf(h4.y, w4.y, s);
        s = fmaf(h4.z, w4.z, s); s = fmaf(h4.w, w4.w, s);
    }
    sv[tid] = s;
    __syncthreads();
    for (int r = 0; r < 16; r++) {
        rv[tid] = sv[tid]; ri[tid] = tid;
        __syncthreads();
        for (int off = 64; off; off >>= 1) {
            if (tid < off) {
                float v2 = rv[tid + off]; int i2 = ri[tid + off];
                if (v2 > rv[tid] || (v2 == rv[tid] && i2 < ri[tid])) { rv[tid] = v2; ri[tid] = i2; }
            }
            __syncthreads();
        }
        if (tid == 0) {
            g_topidx[b * 16 + r] = ri[0];
            g_topval[b * 16 + r] = rv[0];
            sv[ri[0]] = -FLT_MAX;
        }
        __syncthreads();
    }
}

// ---------------- head: amp, pos/atom argmax, scatter -----------------------
__global__ __launch_bounds__(128) void scatter_kernel(const float* __restrict__ amp_w,
                                                      const float* __restrict__ amp_b,
                                                      const float* __restrict__ pos_w,
                                                      const float* __restrict__ pos_b,
                                                      const float* __restrict__ atom_w,
                                                      const float* __restrict__ atom_b,
                                                      const float* __restrict__ dmat,
                                                      float* __restrict__ out)
{
    const int rk = blockIdx.x, b = blockIdx.y, tid = threadIdx.x;
    __shared__ __align__(16) float vec[128];
    __shared__ float rv[128];
    __shared__ int ri[128];
    __shared__ float amp_s;
    __shared__ int jstar_s, astar_s;

    int id = g_topidx[b * 16 + rk];
    float val = g_topval[b * 16 + rk];
    vec[tid] = g_h[(size_t)(b * NF + id) * DM + tid] * val;
    __syncthreads();

    rv[tid] = vec[tid] * amp_w[tid];
    __syncthreads();
    for (int off = 64; off; off >>= 1) {
        if (tid < off) rv[tid] += rv[tid + off];
        __syncthreads();
    }
    if (tid == 0) amp_s = fmaxf(rv[0] + amp_b[0], 0.f);
    __syncthreads();

    const float4* vp = (const float4*)vec;

    float bv = -FLT_MAX; int bi = 1 << 30;
#pragma unroll
    for (int q = 0; q < 4; q++) {
        int o = q * 128 + tid;
        const float4* wp = (const float4*)(pos_w + (size_t)o * DM);
        float lg = pos_b[o];
#pragma unroll
        for (int i = 0; i < 32; i++) {
            float4 w4 = wp[i], v4 = vp[i];
            lg = fmaf(w4.x, v4.x, lg); lg = fmaf(w4.y, v4.y, lg);
            lg = fmaf(w4.z, v4.z, lg); lg = fmaf(w4.w, v4.w, lg);
        }
        if (lg > bv || (lg == bv && o < bi)) { bv = lg; bi = o; }
    }
    rv[tid] = bv; ri[tid] = bi;
    __syncthreads();
    for (int off = 64; off; off >>= 1) {
        if (tid < off) {
            float v2 = rv[tid + off]; int i2 = ri[tid + off];
            if (v2 > rv[tid] || (v2 == rv[tid] && i2 < ri[tid])) { rv[tid] = v2; ri[tid] = i2; }
        }
        __syncthreads();
    }
    if (tid == 0) jstar_s = ri[0];
    __syncthreads();

    bv = -FLT_MAX; bi = 1 << 30;
#pragma unroll
    for (int q = 0; q < 2; q++) {
        int o = q * 128 + tid;
        const float4* wp = (const float4*)(atom_w + (size_t)o * DM);
        float lg = atom_b[o];
#pragma unroll
        for (int i = 0; i < 32; i++) {
            float4 w4 = wp[i], v4 = vp[i];
            lg = fmaf(w4.x, v4.x, lg); lg = fmaf(w4.y, v4.y, lg);
            lg = fmaf(w4.z, v4.z, lg); lg = fmaf(w4.w, v4.w, lg);
        }
        if (lg > bv || (lg == bv && o < bi)) { bv = lg; bi = o; }
    }
    rv[tid] = bv; ri[tid] = bi;
    __syncthreads();
    for (int off = 64; off; off >>= 1) {
        if (tid < off) {
            float v2 = rv[tid + off]; int i2 = ri[tid + off];
            if (v2 > rv[tid] || (v2 == rv[tid] && i2 < ri[tid])) { rv[tid] = v2; ri[tid] = i2; }
        }
        __syncthreads();
    }
    if (tid == 0) astar_s = ri[0];
    __syncthreads();

    float amp = amp_s;
    int p = jstar_s * 64;
    int a = astar_s;
    for (int i = tid; i < 256; i += 128) {
        int t = p + i;
        if (t < NS)
            atomicAdd(out + (size_t)b * NS + t, dmat[(size_t)a * 256 + i] * amp);
    }
}

// ---------------------------------------------------------------------------
extern "C" void kernel_launch(void* const* d_in, const int* in_sizes, int n_in,
                              void* d_out, int out_size)
{
    const float* x         = (const float*)d_in[0];
    const float* fb        = (const float*)d_in[1];
    const float* embed_w   = (const float*)d_in[2];
    const float* embed_b   = (const float*)d_in[3];
    const float* in_proj_w = (const float*)d_in[4];
    const float* in_proj_b = (const float*)d_in[5];
    const float* out_w     = (const float*)d_in[6];
    const float* out_b     = (const float*)d_in[7];
    const float* lin1_w    = (const float*)d_in[8];
    const float* lin1_b    = (const float*)d_in[9];
    const float* lin2_w    = (const float*)d_in[10];
    const float* lin2_b    = (const float*)d_in[11];
    const float* ln1_w     = (const float*)d_in[12];
    const float* ln1_b     = (const float*)d_in[13];
    const float* ln2_w     = (const float*)d_in[14];
    const float* ln2_b     = (const float*)d_in[15];
    const float* attn_w    = (const float*)d_in[16];
    const float* attn_b    = (const float*)d_in[17];
    const float* amp_w     = (const float*)d_in[18];
    const float* amp_b     = (const float*)d_in[19];
    const float* pos_w     = (const float*)d_in[20];
    const float* pos_b     = (const float*)d_in[21];
    const float* atom_w    = (const float*)d_in[22];
    const float* atom_b    = (const float*)d_in[23];
    const float* dmat      = (const float*)d_in[24];
    float* out = (float*)d_out;

    float *p_h, *p_qkv, *p_attno, *p_tmp, *p_ff;
    cudaGetSymbolAddress((void**)&p_h, g_h);
    cudaGetSymbolAddress((void**)&p_qkv, g_qkv);
    cudaGetSymbolAddress((void**)&p_attno, g_attno);
    cudaGetSymbolAddress((void**)&p_tmp, g_tmp);
    cudaGetSymbolAddress((void**)&p_ff, g_ff);

    split_x_kernel<<<(NB * NS + 255) / 256, 256>>>(x);
    split_w_kernel<<<(128 * 512 + 255) / 256, 256>>>(fb);

    cudaFuncSetAttribute(conv_mma_kernel, cudaFuncAttributeMaxDynamicSharedMemorySize, CONV_SMEM);
    conv_mma_kernel<<<dim3(NF, NB), 512, CONV_SMEM>>>(x);

    embed_kernel<<<NB * NF, 128>>>(embed_w, embed_b);

    for (int i = 0; i < 6; i++) {
        linear_kernel<3, false><<<512, 128>>>(p_h, in_proj_w + (size_t)i * 384 * 128,
                                              in_proj_b + i * 384, p_qkv);
        attn_kernel<<<dim3(4, NB), 128>>>();
        linear_kernel<1, false><<<512, 128>>>(p_attno, out_w + (size_t)i * 128 * 128,
                                              out_b + i * 128, p_tmp);
        addln_kernel<<<NB * NF, 128>>>(p_h, p_tmp, ln1_w + i * 128, ln1_b + i * 128);
        linear_kernel<1, true><<<512, 128>>>(p_h, lin1_w + (size_t)i * 128 * 128,
                                             lin1_b + i * 128, p_ff);
        linear_kernel<1, false><<<512, 128>>>(p_ff, lin2_w + (size_t)i * 128 * 128,
                                              lin2_b + i * 128, p_tmp);
        addln_kernel<<<NB * NF, 128>>>(p_h, p_tmp, ln2_w + i * 128, ln2_b + i * 128);
    }

    topk_kernel<<<NB, 128>>>(attn_w, attn_b);
    cudaMemsetAsync(d_out, 0, (size_t)out_size * sizeof(float), 0);
    scatter_kernel<<<dim3(16, NB), 128>>>(amp_w, amp_b, pos_w, pos_b,
                                          atom_w, atom_b, dmat, out);
}